// round 16
// baseline (speedup 1.0000x reference)
#include <cuda_runtime.h>
#include <cuda_fp16.h>
#include <mma.h>
#include <math.h>
#include <stdint.h>

using namespace nvcuda;

#define TOK   2048
#define DIMK  1024
#define HIDN  4096
#define NEXP  7
#define NE_ALL 8
#define ALPHA_C 2.0f

// ---------------------------------------------------------------------------
// Scratch
// ---------------------------------------------------------------------------
__device__ int   g_eidx[TOK];
__device__ float g_scale[TOK];
__device__ int   g_perm[TOK];
__device__ int   g_off[NEXP + 1];
__device__ __align__(128) __half g_xh[(size_t)TOK * DIMK];
__device__ __align__(128) __half g_hrh[(size_t)TOK * HIDN];
__device__ __align__(128) __half g_hsh[(size_t)TOK * HIDN];
__device__ __align__(128) __half g_wgh[(size_t)NEXP * DIMK * HIDN];
__device__ __align__(128) __half g_wuh[(size_t)NEXP * DIMK * HIDN];
__device__ __align__(128) __half g_wdh[(size_t)NEXP * HIDN * DIMK];
__device__ __align__(128) __half g_wsgh[(size_t)DIMK * HIDN];
__device__ __align__(128) __half g_wsuh[(size_t)DIMK * HIDN];
__device__ __align__(128) __half g_wsdh[(size_t)HIDN * DIMK];

// ---------------------------------------------------------------------------
// helpers
// ---------------------------------------------------------------------------
__device__ __forceinline__ void cp_async16(void* smem_dst, const void* gmem_src) {
    uint32_t s = (uint32_t)__cvta_generic_to_shared(smem_dst);
    asm volatile("cp.async.cg.shared.global [%0], [%1], 16;\n" :: "r"(s), "l"(gmem_src));
}
__device__ __forceinline__ void cp_commit() { asm volatile("cp.async.commit_group;\n"); }
template <int N> __device__ __forceinline__ void cp_wait() {
    asm volatile("cp.async.wait_group %0;\n" :: "n"(N));
}
__device__ __forceinline__ float silu_f(float v) { return v / (1.0f + expf(-v)); }

__device__ __forceinline__ void red_add_v2(float* addr, float v0, float v1) {
    asm volatile("red.global.add.v2.f32 [%0], {%1, %2};"
                 :: "l"(addr), "f"(v0), "f"(v1) : "memory");
}

__global__ void f2h_kernel(const float4* __restrict__ s, uint4* __restrict__ d, int n8) {
    int i = blockIdx.x * blockDim.x + threadIdx.x;
    if (i >= n8) return;
    float4 v0 = s[2 * i], v1 = s[2 * i + 1];
    __half2 h0 = __floats2half2_rn(v0.x, v0.y);
    __half2 h1 = __floats2half2_rn(v0.z, v0.w);
    __half2 h2 = __floats2half2_rn(v1.x, v1.y);
    __half2 h3 = __floats2half2_rn(v1.z, v1.w);
    uint4 o;
    o.x = *reinterpret_cast<unsigned*>(&h0);
    o.y = *reinterpret_cast<unsigned*>(&h1);
    o.z = *reinterpret_cast<unsigned*>(&h2);
    o.w = *reinterpret_cast<unsigned*>(&h3);
    d[i] = o;
}
__global__ void zero4_kernel(float4* __restrict__ d, int n4) {
    int i = blockIdx.x * blockDim.x + threadIdx.x;
    if (i < n4) d[i] = make_float4(0.f, 0.f, 0.f, 0.f);
}

// ---------------------------------------------------------------------------
// Router (fp32 exact) + plan
// ---------------------------------------------------------------------------
__global__ void router_kernel(const float* __restrict__ x, const float* __restrict__ wr) {
    int gw   = (blockIdx.x * blockDim.x + threadIdx.x) >> 5;
    int lane = threadIdx.x & 31;
    if (gw >= TOK) return;
    const float* xr = x + (size_t)gw * DIMK;
    float acc[NE_ALL];
#pragma unroll
    for (int e = 0; e < NE_ALL; e++) acc[e] = 0.f;
    for (int d = lane; d < DIMK; d += 32) {
        float xv = xr[d];
        const float4* w4 = reinterpret_cast<const float4*>(wr + (size_t)d * NE_ALL);
        float4 w0 = w4[0], w1 = w4[1];
        acc[0] += xv * w0.x; acc[1] += xv * w0.y;
        acc[2] += xv * w0.z; acc[3] += xv * w0.w;
        acc[4] += xv * w1.x; acc[5] += xv * w1.y;
        acc[6] += xv * w1.z; acc[7] += xv * w1.w;
    }
#pragma unroll
    for (int e = 0; e < NE_ALL; e++)
#pragma unroll
        for (int o = 16; o > 0; o >>= 1)
            acc[e] += __shfl_xor_sync(0xffffffffu, acc[e], o);
    if (lane == 0) {
        float m = acc[0]; int idx = 0;
#pragma unroll
        for (int e = 1; e < NE_ALL; e++)
            if (acc[e] > m) { m = acc[e]; idx = e; }
        float s = 0.f;
#pragma unroll
        for (int e = 0; e < NE_ALL; e++) s += expf(acc[e] - m);
        g_scale[gw] = ALPHA_C / s;
        g_eidx[gw]  = idx;
    }
}
__global__ void plan_kernel() {
    __shared__ int cnt[NEXP], offs[NEXP + 1], cur[NEXP];
    int tid = threadIdx.x;
    if (tid < NEXP) cnt[tid] = 0;
    __syncthreads();
    for (int t = tid; t < TOK; t += blockDim.x) {
        int e = g_eidx[t];
        if (e < NEXP) atomicAdd(&cnt[e], 1);
    }
    __syncthreads();
    if (tid == 0) {
        int o = 0;
        for (int e = 0; e < NEXP; e++) { offs[e] = o; cur[e] = o; o += cnt[e]; }
        offs[NEXP] = o;
    }
    __syncthreads();
    for (int t = tid; t < TOK; t += blockDim.x) {
        int e = g_eidx[t];
        if (e < NEXP) g_perm[atomicAdd(&cur[e], 1)] = t;
    }
    if (tid <= NEXP) g_off[tid] = offs[tid];
}

// ---------------------------------------------------------------------------
// Hidden (fp16): H = half( silu(A@Wg) * (A@Wu) )   (R15 config, unchanged)
// BM=64, 256 threads, block 64x128 dual-B, 8 warps 2x4, warp 32x32.
// BK=32, 3-stage cp.async. 2 CTAs/SM.
// ---------------------------------------------------------------------------
#define H_NT 256
#define H_AP 40
#define H_BP 136
#define H_ASZ (64 * H_AP)
#define H_BSZ (32 * H_BP)
#define H_STG (H_ASZ + 2 * H_BSZ)    // 11264 halves = 22528 B
#define H_SMEM (3 * H_STG * 2)       // 67584 B

__global__ __launch_bounds__(H_NT, 2)
void hidden_kernel(const __half* __restrict__ A,
                   const __half* __restrict__ Wg,
                   const __half* __restrict__ Wu,
                   const __half* __restrict__ Wsg,
                   const __half* __restrict__ Wsu,
                   __half* __restrict__ Hr,
                   __half* __restrict__ Hs) {
    extern __shared__ __align__(16) __half smem[];
    const int K = DIMK, N = HIDN;

    int z = blockIdx.z;
    bool routed = (z < NEXP);
    int off, count;
    const __half *BgP, *BuP;
    __half* H;
    if (routed) {
        off = g_off[z]; count = g_off[z + 1] - off;
        BgP = Wg + (size_t)z * K * N;
        BuP = Wu + (size_t)z * K * N;
        H = Hr;
    } else {
        off = 0; count = TOK;
        BgP = Wsg; BuP = Wsu;
        H = Hs;
    }
    int m0 = blockIdx.x * 64;
    if (m0 >= count) return;
    int n0 = blockIdx.y * 128;

    int tid  = threadIdx.x;
    int warp = tid >> 5;
    int wm   = warp >> 2;
    int wn   = warp & 3;

    int arow;
    {
        int r = tid >> 2;
        int rr = m0 + r;
        if (rr >= count) rr = count - 1;
        arow = routed ? g_perm[off + rr] : rr;
    }
    int ach = (tid & 3) * 8;

    auto load_stage = [&](int kt, int s) {
        __half* As = smem + (size_t)s * H_STG;
        __half* Bg = As + H_ASZ;
        __half* Bu = Bg + H_BSZ;
        {
            int r = tid >> 2;
            cp_async16(As + r * H_AP + ach,
                       A + (size_t)arow * K + kt * 32 + ach);
        }
#pragma unroll
        for (int c = 0; c < 4; c++) {
            int slot = tid + c * H_NT;
            int mat = slot >> 9;
            int w   = slot & 511;
            int br  = w >> 4;
            int bc  = (w & 15) * 8;
            const __half* src = (mat ? BuP : BgP) + (size_t)(kt * 32 + br) * N + n0 + bc;
            __half* dst = (mat ? Bu : Bg) + br * H_BP + bc;
            cp_async16(dst, src);
        }
        cp_commit();
    };

    wmma::fragment<wmma::accumulator, 16, 16, 16, float> accg[2][2], accu[2][2];
#pragma unroll
    for (int i = 0; i < 2; i++)
#pragma unroll
        for (int j = 0; j < 2; j++) {
            wmma::fill_fragment(accg[i][j], 0.0f);
            wmma::fill_fragment(accu[i][j], 0.0f);
        }

    const int nk = K / 32;   // 32
    load_stage(0, 0);
    load_stage(1, 1);

    for (int kt = 0; kt < nk; kt++) {
        if (kt + 1 < nk) cp_wait<1>(); else cp_wait<0>();
        __syncthreads();
        if (kt + 2 < nk) load_stage(kt + 2, (kt + 2) % 3);

        __half* As = smem + (size_t)(kt % 3) * H_STG;
        __half* Bg = As + H_ASZ;
        __half* Bu = Bg + H_BSZ;

#pragma unroll
        for (int ks = 0; ks < 2; ks++) {
            wmma::fragment<wmma::matrix_a, 16, 16, 16, __half, wmma::row_major> a[2];
#pragma unroll
            for (int i = 0; i < 2; i++)
                wmma::load_matrix_sync(a[i], As + (wm * 32 + i * 16) * H_AP + ks * 16, H_AP);
#pragma unroll
            for (int j = 0; j < 2; j++) {
                wmma::fragment<wmma::matrix_b, 16, 16, 16, __half, wmma::row_major> bg, bu;
                wmma::load_matrix_sync(bg, Bg + (ks * 16) * H_BP + wn * 32 + j * 16, H_BP);
                wmma::load_matrix_sync(bu, Bu + (ks * 16) * H_BP + wn * 32 + j * 16, H_BP);
#pragma unroll
                for (int i = 0; i < 2; i++) {
                    wmma::mma_sync(accg[i][j], a[i], bg, accg[i][j]);
                    wmma::mma_sync(accu[i][j], a[i], bu, accu[i][j]);
                }
            }
        }
    }

#pragma unroll
    for (int i = 0; i < 2; i++)
#pragma unroll
        for (int j = 0; j < 2; j++)
#pragma unroll
            for (int t = 0; t < accg[i][j].num_elements; t++)
                accg[i][j].x[t] = silu_f(accg[i][j].x[t]) * accu[i][j].x[t];

    __syncthreads();
    float* Cs = reinterpret_cast<float*>(smem);   // 64 x 132 f32
#pragma unroll
    for (int i = 0; i < 2; i++)
#pragma unroll
        for (int j = 0; j < 2; j++)
            wmma::store_matrix_sync(&Cs[(wm * 32 + i * 16) * 132 + wn * 32 + j * 16],
                                    accg[i][j], 132, wmma::mem_row_major);
    __syncthreads();
    for (int lin = tid; lin < 64 * 64; lin += H_NT) {
        int r  = lin >> 6;
        int c2 = (lin & 63) * 2;
        if (m0 + r >= count) continue;
        __half2 hv = __floats2half2_rn(Cs[r * 132 + c2], Cs[r * 132 + c2 + 1]);
        *reinterpret_cast<__half2*>(&H[(size_t)(off + m0 + r) * N + n0 + c2]) = hv;
    }
}

// ---------------------------------------------------------------------------
// Down (fp16, fused shared+routed): out += via red.global.add.v2.f32.
// BM=64 (cuts routed padding ~31% -> ~9%). 256 threads, block 64x128,
// 8 warps 2x4, warp 32x32, BK=64, 3 stages, 2 CTAs/SM.
// ---------------------------------------------------------------------------
#define D_NT 256
#define D_AP 72
#define D_BP 136
#define D_ASZ (64 * D_AP)        // 4608 halves
#define D_BSZ (64 * D_BP)        // 8704 halves
#define D_STG (D_ASZ + D_BSZ)    // 13312 halves = 26624 B
#define D_SMEM (3 * D_STG * 2)   // 79872 B (>= epi 64*132*4 = 33792)

__global__ __launch_bounds__(D_NT, 2)
void down_kernel(const __half* __restrict__ Hr,
                 const __half* __restrict__ Hs,
                 const __half* __restrict__ Wd,
                 const __half* __restrict__ Wsd,
                 float* __restrict__ out) {
    extern __shared__ __align__(16) __half smem[];
    const int K = HIDN, N = DIMK;

    int z = blockIdx.z;
    bool routed = (z < NEXP);
    int off, count;
    const __half *Ap, *Bp;
    if (routed) {
        off = g_off[z]; count = g_off[z + 1] - off;
        Ap = Hr; Bp = Wd + (size_t)z * K * N;
    } else {
        off = 0; count = TOK;
        Ap = Hs; Bp = Wsd;
    }
    int m0 = blockIdx.x * 64;
    if (m0 >= count) return;
    int n0 = blockIdx.y * 128;

    int tid  = threadIdx.x;
    int warp = tid >> 5;
    int wm   = warp >> 2;   // 0..1 (32-row band)
    int wn   = warp & 3;    // 0..3 (32-col band)

    // A rows: 2 slots/thread (512 slots = 64 rows x 8 chunks of 8 halves)
    int arow[2];
#pragma unroll
    for (int c = 0; c < 2; c++) {
        int r = (tid + c * D_NT) >> 3;
        int rr = m0 + r;
        if (rr >= count) rr = count - 1;
        arow[c] = off + rr;
    }

    auto load_stage = [&](int kt, int s) {
        __half* As = smem + (size_t)s * D_STG;
        __half* Bs = As + D_ASZ;
#pragma unroll
        for (int c = 0; c < 2; c++) {
            int slot = tid + c * D_NT;
            int r = slot >> 3;
            int ch = (slot & 7) * 8;
            cp_async16(As + r * D_AP + ch,
                       Ap + (size_t)arow[c] * K + kt * 64 + ch);
        }
#pragma unroll
        for (int c = 0; c < 4; c++) {
            int slot = tid + c * D_NT;       // 0..1023
            int br  = slot >> 4;             // 0..63
            int bc  = (slot & 15) * 8;       // 0..120
            cp_async16(Bs + br * D_BP + bc,
                       Bp + (size_t)(kt * 64 + br) * N + n0 + bc);
        }
        cp_commit();
    };

    wmma::fragment<wmma::accumulator, 16, 16, 16, float> acc[2][2];
#pragma unroll
    for (int i = 0; i < 2; i++)
#pragma unroll
        for (int j = 0; j < 2; j++)
            wmma::fill_fragment(acc[i][j], 0.0f);

    const int nk = K / 64;   // 64
    load_stage(0, 0);
    load_stage(1, 1);

    for (int kt = 0; kt < nk; kt++) {
        if (kt + 1 < nk) cp_wait<1>(); else cp_wait<0>();
        __syncthreads();
        if (kt + 2 < nk) load_stage(kt + 2, (kt + 2) % 3);

        __half* As = smem + (size_t)(kt % 3) * D_STG;
        __half* Bs = As + D_ASZ;

#pragma unroll
        for (int ks = 0; ks < 4; ks++) {
            wmma::fragment<wmma::matrix_a, 16, 16, 16, __half, wmma::row_major> a[2];
#pragma unroll
            for (int i = 0; i < 2; i++)
                wmma::load_matrix_sync(a[i], As + (wm * 32 + i * 16) * D_AP + ks * 16, D_AP);
#pragma unroll
            for (int j = 0; j < 2; j++) {
                wmma::fragment<wmma::matrix_b, 16, 16, 16, __half, wmma::row_major> b;
                wmma::load_matrix_sync(b, Bs + (ks * 16) * D_BP + wn * 32 + j * 16, D_BP);
#pragma unroll
                for (int i = 0; i < 2; i++)
                    wmma::mma_sync(acc[i][j], a[i], b, acc[i][j]);
            }
        }
    }

    __syncthreads();
    float* Cs = reinterpret_cast<float*>(smem);   // 64 x 132
#pragma unroll
    for (int i = 0; i < 2; i++)
#pragma unroll
        for (int j = 0; j < 2; j++)
            wmma::store_matrix_sync(&Cs[(wm * 32 + i * 16) * 132 + wn * 32 + j * 16],
                                    acc[i][j], 132, wmma::mem_row_major);
    __syncthreads();
    for (int lin = tid; lin < 64 * 64; lin += D_NT) {
        int r  = lin >> 6;          // 0..63
        int c2 = (lin & 63) * 2;    // 0..126
        if (m0 + r >= count) continue;
        float v0 = Cs[r * 132 + c2];
        float v1 = Cs[r * 132 + c2 + 1];
        int tok;
        if (routed) {
            tok = g_perm[off + m0 + r];
            float sc = g_scale[tok];
            v0 *= sc; v1 *= sc;
        } else {
            tok = m0 + r;
        }
        red_add_v2(&out[(size_t)tok * N + n0 + c2], v0, v1);
    }
}

// ---------------------------------------------------------------------------
// Launch — two-stream graph (R15 topology)
// ---------------------------------------------------------------------------
extern "C" void kernel_launch(void* const* d_in, const int* in_sizes, int n_in,
                              void* d_out, int out_size) {
    const float* x        = (const float*)d_in[0];
    const float* w_router = (const float*)d_in[1];
    const float* w_up     = (const float*)d_in[2];
    const float* w_gate   = (const float*)d_in[3];
    const float* w_down   = (const float*)d_in[4];
    const float* ws_up    = (const float*)d_in[5];
    const float* ws_gate  = (const float*)d_in[6];
    const float* ws_down  = (const float*)d_in[7];
    float* out = (float*)d_out;

    void* p;
    cudaGetSymbolAddress(&p, g_xh);   __half* xh   = (__half*)p;
    cudaGetSymbolAddress(&p, g_hrh);  __half* hrh  = (__half*)p;
    cudaGetSymbolAddress(&p, g_hsh);  __half* hsh  = (__half*)p;
    cudaGetSymbolAddress(&p, g_wgh);  __half* wgh  = (__half*)p;
    cudaGetSymbolAddress(&p, g_wuh);  __half* wuh  = (__half*)p;
    cudaGetSymbolAddress(&p, g_wdh);  __half* wdh  = (__half*)p;
    cudaGetSymbolAddress(&p, g_wsgh); __half* wsgh = (__half*)p;
    cudaGetSymbolAddress(&p, g_wsuh); __half* wsuh = (__half*)p;
    cudaGetSymbolAddress(&p, g_wsdh); __half* wsdh = (__half*)p;

    cudaFuncSetAttribute(hidden_kernel, cudaFuncAttributeMaxDynamicSharedMemorySize, H_SMEM);
    cudaFuncSetAttribute(down_kernel,   cudaFuncAttributeMaxDynamicSharedMemorySize, D_SMEM);

    static cudaStream_t s2 = nullptr;
    static cudaEvent_t evFork = nullptr, evGU = nullptr, evD = nullptr;
    if (s2 == nullptr) {
        cudaStreamCreateWithFlags(&s2, cudaStreamNonBlocking);
        cudaEventCreateWithFlags(&evFork, cudaEventDisableTiming);
        cudaEventCreateWithFlags(&evGU,   cudaEventDisableTiming);
        cudaEventCreateWithFlags(&evD,    cudaEventDisableTiming);
    }

    const int T = 256;

    cudaEventRecord(evFork, 0);
    cudaStreamWaitEvent(s2, evFork, 0);

    // side stream: zero first (no deps), then conversions in consumer order
    {
        zero4_kernel<<<TOK * DIMK / 4 / T, T, 0, s2>>>((float4*)out, TOK * DIMK / 4);
        int n8 = TOK * DIMK / 8;
        f2h_kernel<<<(n8 + T - 1) / T, T, 0, s2>>>((const float4*)x, (uint4*)xh, n8);
        int n8s = DIMK * HIDN / 8;
        f2h_kernel<<<(n8s + T - 1) / T, T, 0, s2>>>((const float4*)ws_gate, (uint4*)wsgh, n8s);
        f2h_kernel<<<(n8s + T - 1) / T, T, 0, s2>>>((const float4*)ws_up,   (uint4*)wsuh, n8s);
        int n8r = NEXP * DIMK * HIDN / 8;
        f2h_kernel<<<(n8r + T - 1) / T, T, 0, s2>>>((const float4*)w_gate, (uint4*)wgh, n8r);
        f2h_kernel<<<(n8r + T - 1) / T, T, 0, s2>>>((const float4*)w_up,   (uint4*)wuh, n8r);
        cudaEventRecord(evGU, s2);
        f2h_kernel<<<(n8r + T - 1) / T, T, 0, s2>>>((const float4*)w_down, (uint4*)wdh, n8r);
        f2h_kernel<<<(n8s + T - 1) / T, T, 0, s2>>>((const float4*)ws_down, (uint4*)wsdh, n8s);
        cudaEventRecord(evD, s2);
    }

    // default stream: router + plan (concurrent with conversions)
    router_kernel<<<TOK / 8, 256>>>(x, w_router);
    plan_kernel<<<1, 256>>>();

    cudaStreamWaitEvent(0, evGU, 0);
    dim3 grH(TOK / 64, HIDN / 128, NE_ALL);   // 32 x 32 x 8
    hidden_kernel<<<grH, H_NT, H_SMEM>>>(xh, wgh, wuh, wsgh, wsuh, hrh, hsh);

    cudaStreamWaitEvent(0, evD, 0);
    dim3 grD(TOK / 64, DIMK / 128, NE_ALL);   // 32 x 8 x 8 (BM=64 tiles)
    down_kernel<<<grD, D_NT, D_SMEM>>>(hrh, hsh, wdh, wsdh, out);
}

// round 17
// speedup vs baseline: 1.0586x; 1.0586x over previous
#include <cuda_runtime.h>
#include <cuda_fp16.h>
#include <mma.h>
#include <math.h>
#include <stdint.h>

using namespace nvcuda;

#define TOK   2048
#define DIMK  1024
#define HIDN  4096
#define NEXP  7
#define NE_ALL 8
#define ALPHA_C 2.0f

// ---------------------------------------------------------------------------
// Scratch
// ---------------------------------------------------------------------------
__device__ int   g_eidx[TOK];
__device__ float g_scale[TOK];
__device__ int   g_perm[TOK];
__device__ int   g_off[NEXP + 1];
__device__ __align__(128) __half g_xh[(size_t)TOK * DIMK];
__device__ __align__(128) __half g_hrh[(size_t)TOK * HIDN];
__device__ __align__(128) __half g_hsh[(size_t)TOK * HIDN];
__device__ __align__(128) __half g_wgh[(size_t)NEXP * DIMK * HIDN];
__device__ __align__(128) __half g_wuh[(size_t)NEXP * DIMK * HIDN];
__device__ __align__(128) __half g_wdh[(size_t)NEXP * HIDN * DIMK];
__device__ __align__(128) __half g_wsgh[(size_t)DIMK * HIDN];
__device__ __align__(128) __half g_wsuh[(size_t)DIMK * HIDN];
__device__ __align__(128) __half g_wsdh[(size_t)HIDN * DIMK];

// ---------------------------------------------------------------------------
// helpers
// ---------------------------------------------------------------------------
__device__ __forceinline__ void cp_async16(void* smem_dst, const void* gmem_src) {
    uint32_t s = (uint32_t)__cvta_generic_to_shared(smem_dst);
    asm volatile("cp.async.cg.shared.global [%0], [%1], 16;\n" :: "r"(s), "l"(gmem_src));
}
__device__ __forceinline__ void cp_commit() { asm volatile("cp.async.commit_group;\n"); }
template <int N> __device__ __forceinline__ void cp_wait() {
    asm volatile("cp.async.wait_group %0;\n" :: "n"(N));
}
__device__ __forceinline__ float silu_f(float v) { return v / (1.0f + expf(-v)); }

__device__ __forceinline__ void red_add_v2(float* addr, float v0, float v1) {
    asm volatile("red.global.add.v2.f32 [%0], {%1, %2};"
                 :: "l"(addr), "f"(v0), "f"(v1) : "memory");
}

__global__ void f2h_kernel(const float4* __restrict__ s, uint4* __restrict__ d, int n8) {
    int i = blockIdx.x * blockDim.x + threadIdx.x;
    if (i >= n8) return;
    float4 v0 = s[2 * i], v1 = s[2 * i + 1];
    __half2 h0 = __floats2half2_rn(v0.x, v0.y);
    __half2 h1 = __floats2half2_rn(v0.z, v0.w);
    __half2 h2 = __floats2half2_rn(v1.x, v1.y);
    __half2 h3 = __floats2half2_rn(v1.z, v1.w);
    uint4 o;
    o.x = *reinterpret_cast<unsigned*>(&h0);
    o.y = *reinterpret_cast<unsigned*>(&h1);
    o.z = *reinterpret_cast<unsigned*>(&h2);
    o.w = *reinterpret_cast<unsigned*>(&h3);
    d[i] = o;
}
__global__ void zero4_kernel(float4* __restrict__ d, int n4) {
    int i = blockIdx.x * blockDim.x + threadIdx.x;
    if (i < n4) d[i] = make_float4(0.f, 0.f, 0.f, 0.f);
}

// ---------------------------------------------------------------------------
// Router (fp32 exact) + plan
// ---------------------------------------------------------------------------
__global__ void router_kernel(const float* __restrict__ x, const float* __restrict__ wr) {
    int gw   = (blockIdx.x * blockDim.x + threadIdx.x) >> 5;
    int lane = threadIdx.x & 31;
    if (gw >= TOK) return;
    const float* xr = x + (size_t)gw * DIMK;
    float acc[NE_ALL];
#pragma unroll
    for (int e = 0; e < NE_ALL; e++) acc[e] = 0.f;
    for (int d = lane; d < DIMK; d += 32) {
        float xv = xr[d];
        const float4* w4 = reinterpret_cast<const float4*>(wr + (size_t)d * NE_ALL);
        float4 w0 = w4[0], w1 = w4[1];
        acc[0] += xv * w0.x; acc[1] += xv * w0.y;
        acc[2] += xv * w0.z; acc[3] += xv * w0.w;
        acc[4] += xv * w1.x; acc[5] += xv * w1.y;
        acc[6] += xv * w1.z; acc[7] += xv * w1.w;
    }
#pragma unroll
    for (int e = 0; e < NE_ALL; e++)
#pragma unroll
        for (int o = 16; o > 0; o >>= 1)
            acc[e] += __shfl_xor_sync(0xffffffffu, acc[e], o);
    if (lane == 0) {
        float m = acc[0]; int idx = 0;
#pragma unroll
        for (int e = 1; e < NE_ALL; e++)
            if (acc[e] > m) { m = acc[e]; idx = e; }
        float s = 0.f;
#pragma unroll
        for (int e = 0; e < NE_ALL; e++) s += expf(acc[e] - m);
        g_scale[gw] = ALPHA_C / s;
        g_eidx[gw]  = idx;
    }
}
__global__ void plan_kernel() {
    __shared__ int cnt[NEXP], offs[NEXP + 1], cur[NEXP];
    int tid = threadIdx.x;
    if (tid < NEXP) cnt[tid] = 0;
    __syncthreads();
    for (int t = tid; t < TOK; t += blockDim.x) {
        int e = g_eidx[t];
        if (e < NEXP) atomicAdd(&cnt[e], 1);
    }
    __syncthreads();
    if (tid == 0) {
        int o = 0;
        for (int e = 0; e < NEXP; e++) { offs[e] = o; cur[e] = o; o += cnt[e]; }
        offs[NEXP] = o;
    }
    __syncthreads();
    for (int t = tid; t < TOK; t += blockDim.x) {
        int e = g_eidx[t];
        if (e < NEXP) g_perm[atomicAdd(&cur[e], 1)] = t;
    }
    if (tid <= NEXP) g_off[tid] = offs[tid];
}

// ---------------------------------------------------------------------------
// Hidden (fp16): H = half( silu(A@Wg) * (A@Wu) )   (R15 config)
// BM=64, 256 threads, block 64x128 dual-B, 8 warps 2x4, warp 32x32.
// BK=32, 3-stage cp.async. 2 CTAs/SM.
// ---------------------------------------------------------------------------
#define H_NT 256
#define H_AP 40
#define H_BP 136
#define H_ASZ (64 * H_AP)
#define H_BSZ (32 * H_BP)
#define H_STG (H_ASZ + 2 * H_BSZ)    // 11264 halves = 22528 B
#define H_SMEM (3 * H_STG * 2)       // 67584 B

__global__ __launch_bounds__(H_NT, 2)
void hidden_kernel(const __half* __restrict__ A,
                   const __half* __restrict__ Wg,
                   const __half* __restrict__ Wu,
                   const __half* __restrict__ Wsg,
                   const __half* __restrict__ Wsu,
                   __half* __restrict__ Hr,
                   __half* __restrict__ Hs) {
    extern __shared__ __align__(16) __half smem[];
    const int K = DIMK, N = HIDN;

    int z = blockIdx.z;
    bool routed = (z < NEXP);
    int off, count;
    const __half *BgP, *BuP;
    __half* H;
    if (routed) {
        off = g_off[z]; count = g_off[z + 1] - off;
        BgP = Wg + (size_t)z * K * N;
        BuP = Wu + (size_t)z * K * N;
        H = Hr;
    } else {
        off = 0; count = TOK;
        BgP = Wsg; BuP = Wsu;
        H = Hs;
    }
    int m0 = blockIdx.x * 64;
    if (m0 >= count) return;
    int n0 = blockIdx.y * 128;

    int tid  = threadIdx.x;
    int warp = tid >> 5;
    int wm   = warp >> 2;
    int wn   = warp & 3;

    int arow;
    {
        int r = tid >> 2;
        int rr = m0 + r;
        if (rr >= count) rr = count - 1;
        arow = routed ? g_perm[off + rr] : rr;
    }
    int ach = (tid & 3) * 8;

    auto load_stage = [&](int kt, int s) {
        __half* As = smem + (size_t)s * H_STG;
        __half* Bg = As + H_ASZ;
        __half* Bu = Bg + H_BSZ;
        {
            int r = tid >> 2;
            cp_async16(As + r * H_AP + ach,
                       A + (size_t)arow * K + kt * 32 + ach);
        }
#pragma unroll
        for (int c = 0; c < 4; c++) {
            int slot = tid + c * H_NT;
            int mat = slot >> 9;
            int w   = slot & 511;
            int br  = w >> 4;
            int bc  = (w & 15) * 8;
            const __half* src = (mat ? BuP : BgP) + (size_t)(kt * 32 + br) * N + n0 + bc;
            __half* dst = (mat ? Bu : Bg) + br * H_BP + bc;
            cp_async16(dst, src);
        }
        cp_commit();
    };

    wmma::fragment<wmma::accumulator, 16, 16, 16, float> accg[2][2], accu[2][2];
#pragma unroll
    for (int i = 0; i < 2; i++)
#pragma unroll
        for (int j = 0; j < 2; j++) {
            wmma::fill_fragment(accg[i][j], 0.0f);
            wmma::fill_fragment(accu[i][j], 0.0f);
        }

    const int nk = K / 32;   // 32
    load_stage(0, 0);
    load_stage(1, 1);

    for (int kt = 0; kt < nk; kt++) {
        if (kt + 1 < nk) cp_wait<1>(); else cp_wait<0>();
        __syncthreads();
        if (kt + 2 < nk) load_stage(kt + 2, (kt + 2) % 3);

        __half* As = smem + (size_t)(kt % 3) * H_STG;
        __half* Bg = As + H_ASZ;
        __half* Bu = Bg + H_BSZ;

#pragma unroll
        for (int ks = 0; ks < 2; ks++) {
            wmma::fragment<wmma::matrix_a, 16, 16, 16, __half, wmma::row_major> a[2];
#pragma unroll
            for (int i = 0; i < 2; i++)
                wmma::load_matrix_sync(a[i], As + (wm * 32 + i * 16) * H_AP + ks * 16, H_AP);
#pragma unroll
            for (int j = 0; j < 2; j++) {
                wmma::fragment<wmma::matrix_b, 16, 16, 16, __half, wmma::row_major> bg, bu;
                wmma::load_matrix_sync(bg, Bg + (ks * 16) * H_BP + wn * 32 + j * 16, H_BP);
                wmma::load_matrix_sync(bu, Bu + (ks * 16) * H_BP + wn * 32 + j * 16, H_BP);
#pragma unroll
                for (int i = 0; i < 2; i++) {
                    wmma::mma_sync(accg[i][j], a[i], bg, accg[i][j]);
                    wmma::mma_sync(accu[i][j], a[i], bu, accu[i][j]);
                }
            }
        }
    }

#pragma unroll
    for (int i = 0; i < 2; i++)
#pragma unroll
        for (int j = 0; j < 2; j++)
#pragma unroll
            for (int t = 0; t < accg[i][j].num_elements; t++)
                accg[i][j].x[t] = silu_f(accg[i][j].x[t]) * accu[i][j].x[t];

    __syncthreads();
    float* Cs = reinterpret_cast<float*>(smem);   // 64 x 132 f32
#pragma unroll
    for (int i = 0; i < 2; i++)
#pragma unroll
        for (int j = 0; j < 2; j++)
            wmma::store_matrix_sync(&Cs[(wm * 32 + i * 16) * 132 + wn * 32 + j * 16],
                                    accg[i][j], 132, wmma::mem_row_major);
    __syncthreads();
    for (int lin = tid; lin < 64 * 64; lin += H_NT) {
        int r  = lin >> 6;
        int c2 = (lin & 63) * 2;
        if (m0 + r >= count) continue;
        __half2 hv = __floats2half2_rn(Cs[r * 132 + c2], Cs[r * 132 + c2 + 1]);
        *reinterpret_cast<__half2*>(&H[(size_t)(off + m0 + r) * N + n0 + c2]) = hv;
    }
}

// ---------------------------------------------------------------------------
// Down (fp16, fused shared+routed): out += via red.global.add.v2.f32
// (out pre-zeroed). R14 config: 256 threads, block 128x128, BK=64, 3 stages,
// 8 warps 2x4, warp 64x32. 2 CTAs/SM.
// ---------------------------------------------------------------------------
#define D_NT 256
#define D_AP 72
#define D_BP 136
#define D_ASZ (128 * D_AP)
#define D_BSZ (64 * D_BP)
#define D_STG (D_ASZ + D_BSZ)   // 17920 halves = 35840 B
#define D_SMEM (3 * D_STG * 2)  // 107520 B

__global__ __launch_bounds__(D_NT, 2)
void down_kernel(const __half* __restrict__ Hr,
                 const __half* __restrict__ Hs,
                 const __half* __restrict__ Wd,
                 const __half* __restrict__ Wsd,
                 float* __restrict__ out) {
    extern __shared__ __align__(16) __half smem[];
    const int K = HIDN, N = DIMK;

    int z = blockIdx.z;
    bool routed = (z < NEXP);
    int off, count;
    const __half *Ap, *Bp;
    if (routed) {
        off = g_off[z]; count = g_off[z + 1] - off;
        Ap = Hr; Bp = Wd + (size_t)z * K * N;
    } else {
        off = 0; count = TOK;
        Ap = Hs; Bp = Wsd;
    }
    int m0 = blockIdx.x * 128;
    if (m0 >= count) return;
    int n0 = blockIdx.y * 128;

    int tid  = threadIdx.x;
    int warp = tid >> 5;
    int wm   = warp >> 2;
    int wn   = warp & 3;

    int arow[4];
#pragma unroll
    for (int c = 0; c < 4; c++) {
        int r = (tid + c * D_NT) >> 3;
        int rr = m0 + r;
        if (rr >= count) rr = count - 1;
        arow[c] = off + rr;
    }

    auto load_stage = [&](int kt, int s) {
        __half* As = smem + (size_t)s * D_STG;
        __half* Bs = As + D_ASZ;
#pragma unroll
        for (int c = 0; c < 4; c++) {
            int slot = tid + c * D_NT;
            int r = slot >> 3;
            int ch = (slot & 7) * 8;
            cp_async16(As + r * D_AP + ch,
                       Ap + (size_t)arow[c] * K + kt * 64 + ch);
        }
#pragma unroll
        for (int c = 0; c < 4; c++) {
            int slot = tid + c * D_NT;
            int br  = slot >> 4;
            int bc  = (slot & 15) * 8;
            cp_async16(Bs + br * D_BP + bc,
                       Bp + (size_t)(kt * 64 + br) * N + n0 + bc);
        }
        cp_commit();
    };

    wmma::fragment<wmma::accumulator, 16, 16, 16, float> acc[4][2];
#pragma unroll
    for (int i = 0; i < 4; i++)
#pragma unroll
        for (int j = 0; j < 2; j++)
            wmma::fill_fragment(acc[i][j], 0.0f);

    const int nk = K / 64;   // 64
    load_stage(0, 0);
    load_stage(1, 1);

    for (int kt = 0; kt < nk; kt++) {
        if (kt + 1 < nk) cp_wait<1>(); else cp_wait<0>();
        __syncthreads();
        if (kt + 2 < nk) load_stage(kt + 2, (kt + 2) % 3);

        __half* As = smem + (size_t)(kt % 3) * D_STG;
        __half* Bs = As + D_ASZ;

#pragma unroll
        for (int ks = 0; ks < 4; ks++) {
            wmma::fragment<wmma::matrix_a, 16, 16, 16, __half, wmma::row_major> a[4];
            wmma::fragment<wmma::matrix_b, 16, 16, 16, __half, wmma::row_major> b[2];
#pragma unroll
            for (int i = 0; i < 4; i++)
                wmma::load_matrix_sync(a[i], As + (wm * 64 + i * 16) * D_AP + ks * 16, D_AP);
#pragma unroll
            for (int j = 0; j < 2; j++)
                wmma::load_matrix_sync(b[j], Bs + (ks * 16) * D_BP + wn * 32 + j * 16, D_BP);
#pragma unroll
            for (int i = 0; i < 4; i++)
#pragma unroll
                for (int j = 0; j < 2; j++)
                    wmma::mma_sync(acc[i][j], a[i], b[j], acc[i][j]);
        }
    }

    __syncthreads();
    float* Cs = reinterpret_cast<float*>(smem);   // 128 x 132
#pragma unroll
    for (int i = 0; i < 4; i++)
#pragma unroll
        for (int j = 0; j < 2; j++)
            wmma::store_matrix_sync(&Cs[(wm * 64 + i * 16) * 132 + wn * 32 + j * 16],
                                    acc[i][j], 132, wmma::mem_row_major);
    __syncthreads();
    for (int lin = tid; lin < 128 * 64; lin += D_NT) {
        int r  = lin >> 6;
        int c2 = (lin & 63) * 2;
        if (m0 + r >= count) continue;
        float v0 = Cs[r * 132 + c2];
        float v1 = Cs[r * 132 + c2 + 1];
        int tok;
        if (routed) {
            tok = g_perm[off + m0 + r];
            float sc = g_scale[tok];
            v0 *= sc; v1 *= sc;
        } else {
            tok = m0 + r;
        }
        red_add_v2(&out[(size_t)tok * N + n0 + c2], v0, v1);
    }
}

// ---------------------------------------------------------------------------
// Launch — x f2h on default stream; s2: weights (evGU) then zero+down (evD)
// ---------------------------------------------------------------------------
extern "C" void kernel_launch(void* const* d_in, const int* in_sizes, int n_in,
                              void* d_out, int out_size) {
    const float* x        = (const float*)d_in[0];
    const float* w_router = (const float*)d_in[1];
    const float* w_up     = (const float*)d_in[2];
    const float* w_gate   = (const float*)d_in[3];
    const float* w_down   = (const float*)d_in[4];
    const float* ws_up    = (const float*)d_in[5];
    const float* ws_gate  = (const float*)d_in[6];
    const float* ws_down  = (const float*)d_in[7];
    float* out = (float*)d_out;

    void* p;
    cudaGetSymbolAddress(&p, g_xh);   __half* xh   = (__half*)p;
    cudaGetSymbolAddress(&p, g_hrh);  __half* hrh  = (__half*)p;
    cudaGetSymbolAddress(&p, g_hsh);  __half* hsh  = (__half*)p;
    cudaGetSymbolAddress(&p, g_wgh);  __half* wgh  = (__half*)p;
    cudaGetSymbolAddress(&p, g_wuh);  __half* wuh  = (__half*)p;
    cudaGetSymbolAddress(&p, g_wdh);  __half* wdh  = (__half*)p;
    cudaGetSymbolAddress(&p, g_wsgh); __half* wsgh = (__half*)p;
    cudaGetSymbolAddress(&p, g_wsuh); __half* wsuh = (__half*)p;
    cudaGetSymbolAddress(&p, g_wsdh); __half* wsdh = (__half*)p;

    cudaFuncSetAttribute(hidden_kernel, cudaFuncAttributeMaxDynamicSharedMemorySize, H_SMEM);
    cudaFuncSetAttribute(down_kernel,   cudaFuncAttributeMaxDynamicSharedMemorySize, D_SMEM);

    static cudaStream_t s2 = nullptr;
    static cudaEvent_t evFork = nullptr, evGU = nullptr, evD = nullptr;
    if (s2 == nullptr) {
        cudaStreamCreateWithFlags(&s2, cudaStreamNonBlocking);
        cudaEventCreateWithFlags(&evFork, cudaEventDisableTiming);
        cudaEventCreateWithFlags(&evGU,   cudaEventDisableTiming);
        cudaEventCreateWithFlags(&evD,    cudaEventDisableTiming);
    }

    const int T = 256;

    cudaEventRecord(evFork, 0);
    cudaStreamWaitEvent(s2, evFork, 0);

    // side stream: hidden weight conversions first (critical path), then
    // zero + down-weight conversions (overlap with hidden)
    {
        int n8s = DIMK * HIDN / 8;
        f2h_kernel<<<(n8s + T - 1) / T, T, 0, s2>>>((const float4*)ws_gate, (uint4*)wsgh, n8s);
        f2h_kernel<<<(n8s + T - 1) / T, T, 0, s2>>>((const float4*)ws_up,   (uint4*)wsuh, n8s);
        int n8r = NEXP * DIMK * HIDN / 8;
        f2h_kernel<<<(n8r + T - 1) / T, T, 0, s2>>>((const float4*)w_gate, (uint4*)wgh, n8r);
        f2h_kernel<<<(n8r + T - 1) / T, T, 0, s2>>>((const float4*)w_up,   (uint4*)wuh, n8r);
        cudaEventRecord(evGU, s2);
        zero4_kernel<<<TOK * DIMK / 4 / T, T, 0, s2>>>((float4*)out, TOK * DIMK / 4);
        f2h_kernel<<<(n8r + T - 1) / T, T, 0, s2>>>((const float4*)w_down, (uint4*)wdh, n8r);
        f2h_kernel<<<(n8s + T - 1) / T, T, 0, s2>>>((const float4*)ws_down, (uint4*)wsdh, n8s);
        cudaEventRecord(evD, s2);
    }

    // default stream: x conversion + router + plan (all off the s2 chain)
    {
        int n8 = TOK * DIMK / 8;
        f2h_kernel<<<(n8 + T - 1) / T, T>>>((const float4*)x, (uint4*)xh, n8);
    }
    router_kernel<<<TOK / 8, 256>>>(x, w_router);
    plan_kernel<<<1, 256>>>();

    cudaStreamWaitEvent(0, evGU, 0);
    dim3 grH(TOK / 64, HIDN / 128, NE_ALL);   // 32 x 32 x 8
    hidden_kernel<<<grH, H_NT, H_SMEM>>>(xh, wgh, wuh, wsgh, wsuh, hrh, hsh);

    cudaStreamWaitEvent(0, evD, 0);
    dim3 grD(TOK / 128, DIMK / 128, NE_ALL);  // 16 x 8 x 8
    down_kernel<<<grD, D_NT, D_SMEM>>>(hrh, hsh, wdh, wsdh, out);
}